// round 1
// baseline (speedup 1.0000x reference)
#include <cuda_runtime.h>
#include <cstdint>

// Problem constants (fixed by the reference)
#define D_MODEL 1024
#define SEQ     2048
#define BATCH   4
#define NH      16
#define DK      64
#define MROWS   (BATCH * SEQ)   // 8192

// Scratch (no allocations allowed): Q, K, V projections + attention output.
// 4 x 32 MB fp32.
__device__ float g_Q[(size_t)MROWS * D_MODEL];
__device__ float g_K[(size_t)MROWS * D_MODEL];
__device__ float g_V[(size_t)MROWS * D_MODEL];
__device__ float g_A[(size_t)MROWS * D_MODEL];

// ---------------------------------------------------------------------------
// GEMM: C[M,N] = A[M,K] @ W[K,N] + bias[N]
// M=8192, N=1024, K=1024. 128x128 tile, BK=8, 256 threads, 8x8 per thread
// with strided (x16) register tiling for conflict-free smem reads.
// ---------------------------------------------------------------------------
__global__ __launch_bounds__(256) void gemm_bias_kernel(
    const float* __restrict__ A, const float* __restrict__ W,
    const float* __restrict__ bias, float* __restrict__ C)
{
    const int M = MROWS, N = D_MODEL, K = D_MODEL;
    (void)M;
    __shared__ float As[8][128];   // k-major (A transposed on store)
    __shared__ float Bs[8][128];

    const int tid = threadIdx.x;
    const int ty = tid >> 4;       // 0..15
    const int tx = tid & 15;       // 0..15
    const int rowBase = blockIdx.y * 128;
    const int colBase = blockIdx.x * 128;

    // A-tile load: one float4 per thread per k-step (128 rows x 8 k)
    const int aRow = tid >> 1;            // 0..127
    const int aCol = (tid & 1) * 4;       // 0 or 4
    // B-tile load: one float4 per thread (8 rows x 128 cols)
    const int bRow = tid >> 5;            // 0..7
    const int bCol = (tid & 31) * 4;      // 0..124

    float acc[8][8];
#pragma unroll
    for (int i = 0; i < 8; i++)
#pragma unroll
        for (int j = 0; j < 8; j++) acc[i][j] = 0.f;

    const float* Aptr = A + (size_t)(rowBase + aRow) * K + aCol;
    const float* Wptr = W + (size_t)bRow * N + colBase + bCol;

    for (int k0 = 0; k0 < K; k0 += 8) {
        float4 av = *(const float4*)(Aptr + k0);
        As[aCol + 0][aRow] = av.x;
        As[aCol + 1][aRow] = av.y;
        As[aCol + 2][aRow] = av.z;
        As[aCol + 3][aRow] = av.w;
        float4 bv = *(const float4*)(Wptr + (size_t)k0 * N);
        *(float4*)&Bs[bRow][bCol] = bv;
        __syncthreads();
#pragma unroll
        for (int kk = 0; kk < 8; kk++) {
            float a[8], b[8];
#pragma unroll
            for (int i = 0; i < 8; i++) a[i] = As[kk][i * 16 + ty];
#pragma unroll
            for (int j = 0; j < 8; j++) b[j] = Bs[kk][j * 16 + tx];
#pragma unroll
            for (int i = 0; i < 8; i++)
#pragma unroll
                for (int j = 0; j < 8; j++) acc[i][j] += a[i] * b[j];
        }
        __syncthreads();
    }

#pragma unroll
    for (int j = 0; j < 8; j++) {
        const int col = colBase + j * 16 + tx;
        const float bj = bias[col];
#pragma unroll
        for (int i = 0; i < 8; i++) {
            const int row = rowBase + i * 16 + ty;
            C[(size_t)row * N + col] = acc[i][j] + bj;
        }
    }
}

// ---------------------------------------------------------------------------
// Flash attention (fp32, causal). One block per (q-tile of 64, head, batch).
// BR=BC=64, Dk=64. 256 threads (16x16), 4x4 strided micro-tiles.
// smem: sQ[64][65], sKP[64][65] (K tile then reused for P), sV[64][65].
// Causal mask applied analytically (reference mask == triu(k=1)).
// ---------------------------------------------------------------------------
#define ATT_LDS 65
#define ATT_SMEM_BYTES (3 * 64 * ATT_LDS * 4)

__global__ __launch_bounds__(256) void attn_kernel(
    const float* __restrict__ Q, const float* __restrict__ K,
    const float* __restrict__ V, float* __restrict__ O)
{
    extern __shared__ float sm[];
    float* sQ  = sm;
    float* sKP = sm + 64 * ATT_LDS;
    float* sV  = sm + 2 * 64 * ATT_LDS;

    const int tid = threadIdx.x;
    const int ty = tid >> 4;   // 0..15
    const int tx = tid & 15;   // 0..15
    const int qt = blockIdx.x;           // 0..31
    const int h  = blockIdx.y;
    const int b  = blockIdx.z;
    const int q0 = qt * 64;
    const size_t baseRow = (size_t)b * SEQ;
    const int hcol = h * DK;

    // Load Q tile
    for (int idx = tid; idx < 64 * 64; idx += 256) {
        const int r = idx >> 6, d = idx & 63;
        sQ[r * ATT_LDS + d] = Q[(baseRow + q0 + r) * D_MODEL + hcol + d];
    }

    float m[4], l[4], o[4][4];
#pragma unroll
    for (int i = 0; i < 4; i++) {
        m[i] = -1e30f; l[i] = 0.f;
#pragma unroll
        for (int j = 0; j < 4; j++) o[i][j] = 0.f;
    }

    for (int kt = 0; kt <= qt; kt++) {
        const int k0 = kt * 64;
        __syncthreads();  // protect sKP (P of previous iter) and first-iter Q
        for (int idx = tid; idx < 64 * 64; idx += 256) {
            const int r = idx >> 6, d = idx & 63;
            sKP[r * ATT_LDS + d] = K[(baseRow + k0 + r) * D_MODEL + hcol + d];
            sV [r * ATT_LDS + d] = V[(baseRow + k0 + r) * D_MODEL + hcol + d];
        }
        __syncthreads();

        // S = Q @ K^T  (4x4 per thread)
        float s[4][4];
#pragma unroll
        for (int i = 0; i < 4; i++)
#pragma unroll
            for (int j = 0; j < 4; j++) s[i][j] = 0.f;

        for (int d = 0; d < 64; d++) {
            float a[4], bb[4];
#pragma unroll
            for (int i = 0; i < 4; i++) a[i]  = sQ [(i * 16 + ty) * ATT_LDS + d];
#pragma unroll
            for (int j = 0; j < 4; j++) bb[j] = sKP[(j * 16 + tx) * ATT_LDS + d];
#pragma unroll
            for (int i = 0; i < 4; i++)
#pragma unroll
                for (int j = 0; j < 4; j++) s[i][j] += a[i] * bb[j];
        }

        const float scale = 0.125f;  // 1/sqrt(64)
        if (kt == qt) {
#pragma unroll
            for (int i = 0; i < 4; i++) {
                const int rl = i * 16 + ty;
#pragma unroll
                for (int j = 0; j < 4; j++) {
                    const int cl = j * 16 + tx;
                    s[i][j] = (cl > rl) ? -1e30f : s[i][j] * scale;
                }
            }
        } else {
#pragma unroll
            for (int i = 0; i < 4; i++)
#pragma unroll
                for (int j = 0; j < 4; j++) s[i][j] *= scale;
        }

        // Online softmax (row reduction across the 16 tx-lanes of each row)
        float p[4][4];
#pragma unroll
        for (int i = 0; i < 4; i++) {
            float mx = s[i][0];
#pragma unroll
            for (int j = 1; j < 4; j++) mx = fmaxf(mx, s[i][j]);
#pragma unroll
            for (int off = 1; off < 16; off <<= 1)
                mx = fmaxf(mx, __shfl_xor_sync(0xffffffffu, mx, off));
            const float mnew = fmaxf(m[i], mx);
            const float aexp = __expf(m[i] - mnew);
            float rsum = 0.f;
#pragma unroll
            for (int j = 0; j < 4; j++) {
                p[i][j] = __expf(s[i][j] - mnew);
                rsum += p[i][j];
            }
#pragma unroll
            for (int off = 1; off < 16; off <<= 1)
                rsum += __shfl_xor_sync(0xffffffffu, rsum, off);
            l[i] = l[i] * aexp + rsum;
            m[i] = mnew;
#pragma unroll
            for (int j = 0; j < 4; j++) o[i][j] *= aexp;
        }

        __syncthreads();  // GEMM1 done reading K tile -> safe to overwrite with P
#pragma unroll
        for (int i = 0; i < 4; i++)
#pragma unroll
            for (int j = 0; j < 4; j++)
                sKP[(i * 16 + ty) * ATT_LDS + (j * 16 + tx)] = p[i][j];
        __syncthreads();

        // O += P @ V
        for (int c = 0; c < 64; c++) {
            float pp[4], vv[4];
#pragma unroll
            for (int i = 0; i < 4; i++) pp[i] = sKP[(i * 16 + ty) * ATT_LDS + c];
#pragma unroll
            for (int j = 0; j < 4; j++) vv[j] = sV[c * ATT_LDS + (j * 16 + tx)];
#pragma unroll
            for (int i = 0; i < 4; i++)
#pragma unroll
                for (int j = 0; j < 4; j++) o[i][j] += pp[i] * vv[j];
        }
    }

    // Normalize + store
#pragma unroll
    for (int i = 0; i < 4; i++) {
        const float inv = 1.f / l[i];
        const int rg = q0 + i * 16 + ty;
#pragma unroll
        for (int j = 0; j < 4; j++)
            O[(baseRow + rg) * D_MODEL + hcol + (j * 16 + tx)] = o[i][j] * inv;
    }
}

// ---------------------------------------------------------------------------
// Launch: QKV projections -> flash attention -> output projection.
// Inputs (metadata order): 0 context, 1 value, 2 mask(ignored), 3 Wq, 4 bq,
// 5 Wk, 6 bk, 7 Wv, 8 bv, 9 Wo, 10 bo.
// ---------------------------------------------------------------------------
extern "C" void kernel_launch(void* const* d_in, const int* in_sizes, int n_in,
                              void* d_out, int out_size)
{
    (void)in_sizes; (void)n_in; (void)out_size;
    const float* ctx = (const float*)d_in[0];
    const float* val = (const float*)d_in[1];
    const float* Wq  = (const float*)d_in[3];
    const float* bq  = (const float*)d_in[4];
    const float* Wk  = (const float*)d_in[5];
    const float* bk  = (const float*)d_in[6];
    const float* Wv  = (const float*)d_in[7];
    const float* bv  = (const float*)d_in[8];
    const float* Wo  = (const float*)d_in[9];
    const float* bo  = (const float*)d_in[10];
    float* out = (float*)d_out;

    float *qp, *kp, *vp, *ap;
    cudaGetSymbolAddress((void**)&qp, g_Q);
    cudaGetSymbolAddress((void**)&kp, g_K);
    cudaGetSymbolAddress((void**)&vp, g_V);
    cudaGetSymbolAddress((void**)&ap, g_A);

    cudaFuncSetAttribute(attn_kernel,
                         cudaFuncAttributeMaxDynamicSharedMemorySize,
                         ATT_SMEM_BYTES);

    dim3 gblock(256);
    dim3 ggrid(D_MODEL / 128, MROWS / 128);  // (8, 64)

    gemm_bias_kernel<<<ggrid, gblock>>>(ctx, Wq, bq, qp);
    gemm_bias_kernel<<<ggrid, gblock>>>(ctx, Wk, bk, kp);
    gemm_bias_kernel<<<ggrid, gblock>>>(val, Wv, bv, vp);

    dim3 agrid(SEQ / 64, NH, BATCH);  // (32, 16, 4)
    attn_kernel<<<agrid, 256, ATT_SMEM_BYTES>>>(qp, kp, vp, ap);

    gemm_bias_kernel<<<ggrid, gblock>>>(ap, Wo, bo, out);
}

// round 2
// speedup vs baseline: 1.7526x; 1.7526x over previous
#include <cuda_runtime.h>
#include <cstdint>

// Problem constants (fixed by the reference)
#define D_MODEL 1024
#define SEQ     2048
#define BATCH   4
#define NH      16
#define DK      64
#define MROWS   (BATCH * SEQ)   // 8192

// Scratch (no allocations allowed): Q, K, V projections + attention output.
__device__ float g_Q[(size_t)MROWS * D_MODEL];
__device__ float g_K[(size_t)MROWS * D_MODEL];
__device__ float g_V[(size_t)MROWS * D_MODEL];
__device__ float g_A[(size_t)MROWS * D_MODEL];

// ---------------------------------------------------------------------------
// TF32 tensor-core GEMM: C[M,N] = A[M,K] @ W[K,N] + bias[N]
// M=8192, N=K=1024. Block tile 128x128x32, 8 warps (64x32 warp tiles),
// mma.sync.m16n8k8.tf32, double-buffered smem with register prefetch.
// Inputs converted to tf32 with cvt.rna at smem-store time.
// ---------------------------------------------------------------------------
#define BM 128
#define BN 128
#define BK 32
#define APITCH 36     // pad so A-frag LDS (row*36+col) covers all 32 banks
#define BPITCH 136    // pad so B-frag LDS (k*136+col) covers all 32 banks
#define ASTG (BM * APITCH)   // 4608 floats
#define BSTG (BK * BPITCH)   // 4352 floats
#define GEMM_SMEM_BYTES (2 * (ASTG + BSTG) * 4)   // 71680

__device__ __forceinline__ float f2tf32(float x) {
    uint32_t r;
    asm("cvt.rna.tf32.f32 %0, %1;" : "=r"(r) : "f"(x));
    return __uint_as_float(r);
}

__device__ __forceinline__ void mma_tf32(
    float& c0, float& c1, float& c2, float& c3,
    uint32_t a0, uint32_t a1, uint32_t a2, uint32_t a3,
    uint32_t b0, uint32_t b1)
{
    asm volatile(
        "mma.sync.aligned.m16n8k8.row.col.f32.tf32.tf32.f32 "
        "{%0,%1,%2,%3}, {%4,%5,%6,%7}, {%8,%9}, {%0,%1,%2,%3};"
        : "+f"(c0), "+f"(c1), "+f"(c2), "+f"(c3)
        : "r"(a0), "r"(a1), "r"(a2), "r"(a3), "r"(b0), "r"(b1));
}

__global__ __launch_bounds__(256) void gemm_tf32_kernel(
    const float* __restrict__ A, const float* __restrict__ W,
    const float* __restrict__ bias, float* __restrict__ C)
{
    const int N = D_MODEL, K = D_MODEL;
    extern __shared__ float sm[];
    float* As = sm;                 // [2][ASTG]
    float* Bs = sm + 2 * ASTG;      // [2][BSTG]

    const int tid  = threadIdx.x;
    const int lane = tid & 31;
    const int warp = tid >> 5;
    const int wm = (warp >> 2) * 64;   // 0 or 64
    const int wn = (warp & 3) * 32;    // 0,32,64,96
    const int rowBase = blockIdx.y * BM;
    const int colBase = blockIdx.x * BN;

    // Global-load coordinates
    const int ar = tid >> 3;          // 0..31 (A rows, step 32)
    const int ac = (tid & 7) * 4;     // 0..28
    const int br = tid >> 5;          // 0..7  (B k-rows, step 8)
    const int bc = (tid & 31) * 4;    // 0..124

    const float* Abase = A + (size_t)(rowBase + ar) * K + ac;
    const float* Wbase = W + (size_t)br * N + colBase + bc;

    float acc[4][4][4];
#pragma unroll
    for (int i = 0; i < 4; i++)
#pragma unroll
        for (int j = 0; j < 4; j++)
#pragma unroll
            for (int q = 0; q < 4; q++) acc[i][j][q] = 0.f;

    float4 aReg[4], bReg[4];

    // Prologue: fetch tile 0
#pragma unroll
    for (int i = 0; i < 4; i++) {
        aReg[i] = *(const float4*)(Abase + (size_t)(32 * i) * K);
        bReg[i] = *(const float4*)(Wbase + (size_t)(8 * i) * N);
    }
#pragma unroll
    for (int i = 0; i < 4; i++) {
        float* d = &As[(ar + 32 * i) * APITCH + ac];
        d[0] = f2tf32(aReg[i].x); d[1] = f2tf32(aReg[i].y);
        d[2] = f2tf32(aReg[i].z); d[3] = f2tf32(aReg[i].w);
        float* e = &Bs[(br + 8 * i) * BPITCH + bc];
        e[0] = f2tf32(bReg[i].x); e[1] = f2tf32(bReg[i].y);
        e[2] = f2tf32(bReg[i].z); e[3] = f2tf32(bReg[i].w);
    }
    __syncthreads();

    int stage = 0;
    for (int k0 = 0; k0 < K; k0 += BK) {
        const bool more = (k0 + BK) < K;
        if (more) {
#pragma unroll
            for (int i = 0; i < 4; i++) {
                aReg[i] = *(const float4*)(Abase + (size_t)(32 * i) * K + k0 + BK);
                bReg[i] = *(const float4*)(Wbase + (size_t)(k0 + BK + 8 * i) * N);
            }
        }

        const float* Acur = As + stage * ASTG;
        const float* Bcur = Bs + stage * BSTG;
#pragma unroll
        for (int kk = 0; kk < BK; kk += 8) {
            uint32_t af[4][4], bf[4][2];
#pragma unroll
            for (int i = 0; i < 4; i++) {
                const int r0 = wm + i * 16 + (lane >> 2);
                const int cc = kk + (lane & 3);
                af[i][0] = __float_as_uint(Acur[r0 * APITCH + cc]);
                af[i][1] = __float_as_uint(Acur[(r0 + 8) * APITCH + cc]);
                af[i][2] = __float_as_uint(Acur[r0 * APITCH + cc + 4]);
                af[i][3] = __float_as_uint(Acur[(r0 + 8) * APITCH + cc + 4]);
            }
#pragma unroll
            for (int j = 0; j < 4; j++) {
                const int cl = wn + j * 8 + (lane >> 2);
                const int kr = kk + (lane & 3);
                bf[j][0] = __float_as_uint(Bcur[kr * BPITCH + cl]);
                bf[j][1] = __float_as_uint(Bcur[(kr + 4) * BPITCH + cl]);
            }
#pragma unroll
            for (int i = 0; i < 4; i++)
#pragma unroll
                for (int j = 0; j < 4; j++)
                    mma_tf32(acc[i][j][0], acc[i][j][1], acc[i][j][2], acc[i][j][3],
                             af[i][0], af[i][1], af[i][2], af[i][3],
                             bf[j][0], bf[j][1]);
        }

        if (more) {
            float* Anx = As + (stage ^ 1) * ASTG;
            float* Bnx = Bs + (stage ^ 1) * BSTG;
#pragma unroll
            for (int i = 0; i < 4; i++) {
                float* d = &Anx[(ar + 32 * i) * APITCH + ac];
                d[0] = f2tf32(aReg[i].x); d[1] = f2tf32(aReg[i].y);
                d[2] = f2tf32(aReg[i].z); d[3] = f2tf32(aReg[i].w);
                float* e = &Bnx[(br + 8 * i) * BPITCH + bc];
                e[0] = f2tf32(bReg[i].x); e[1] = f2tf32(bReg[i].y);
                e[2] = f2tf32(bReg[i].z); e[3] = f2tf32(bReg[i].w);
            }
        }
        __syncthreads();
        stage ^= 1;
    }

    // Epilogue: C = acc + bias
#pragma unroll
    for (int j = 0; j < 4; j++) {
        const int col = colBase + wn + j * 8 + 2 * (lane & 3);
        const float b0 = bias[col], b1 = bias[col + 1];
#pragma unroll
        for (int i = 0; i < 4; i++) {
            const int r0 = rowBase + wm + i * 16 + (lane >> 2);
            float2 v0 = make_float2(acc[i][j][0] + b0, acc[i][j][1] + b1);
            float2 v1 = make_float2(acc[i][j][2] + b0, acc[i][j][3] + b1);
            *(float2*)&C[(size_t)r0 * N + col] = v0;
            *(float2*)&C[(size_t)(r0 + 8) * N + col] = v1;
        }
    }
}

// ---------------------------------------------------------------------------
// Flash attention (fp32, causal) — unchanged from Round 1.
// ---------------------------------------------------------------------------
#define ATT_LDS 65
#define ATT_SMEM_BYTES (3 * 64 * ATT_LDS * 4)

__global__ __launch_bounds__(256) void attn_kernel(
    const float* __restrict__ Q, const float* __restrict__ K,
    const float* __restrict__ V, float* __restrict__ O)
{
    extern __shared__ float sm[];
    float* sQ  = sm;
    float* sKP = sm + 64 * ATT_LDS;
    float* sV  = sm + 2 * 64 * ATT_LDS;

    const int tid = threadIdx.x;
    const int ty = tid >> 4;
    const int tx = tid & 15;
    const int qt = blockIdx.x;
    const int h  = blockIdx.y;
    const int b  = blockIdx.z;
    const int q0 = qt * 64;
    const size_t baseRow = (size_t)b * SEQ;
    const int hcol = h * DK;

    for (int idx = tid; idx < 64 * 64; idx += 256) {
        const int r = idx >> 6, d = idx & 63;
        sQ[r * ATT_LDS + d] = Q[(baseRow + q0 + r) * D_MODEL + hcol + d];
    }

    float m[4], l[4], o[4][4];
#pragma unroll
    for (int i = 0; i < 4; i++) {
        m[i] = -1e30f; l[i] = 0.f;
#pragma unroll
        for (int j = 0; j < 4; j++) o[i][j] = 0.f;
    }

    for (int kt = 0; kt <= qt; kt++) {
        const int k0 = kt * 64;
        __syncthreads();
        for (int idx = tid; idx < 64 * 64; idx += 256) {
            const int r = idx >> 6, d = idx & 63;
            sKP[r * ATT_LDS + d] = K[(baseRow + k0 + r) * D_MODEL + hcol + d];
            sV [r * ATT_LDS + d] = V[(baseRow + k0 + r) * D_MODEL + hcol + d];
        }
        __syncthreads();

        float s[4][4];
#pragma unroll
        for (int i = 0; i < 4; i++)
#pragma unroll
            for (int j = 0; j < 4; j++) s[i][j] = 0.f;

        for (int d = 0; d < 64; d++) {
            float a[4], bb[4];
#pragma unroll
            for (int i = 0; i < 4; i++) a[i]  = sQ [(i * 16 + ty) * ATT_LDS + d];
#pragma unroll
            for (int j = 0; j < 4; j++) bb[j] = sKP[(j * 16 + tx) * ATT_LDS + d];
#pragma unroll
            for (int i = 0; i < 4; i++)
#pragma unroll
                for (int j = 0; j < 4; j++) s[i][j] += a[i] * bb[j];
        }

        const float scale = 0.125f;
        if (kt == qt) {
#pragma unroll
            for (int i = 0; i < 4; i++) {
                const int rl = i * 16 + ty;
#pragma unroll
                for (int j = 0; j < 4; j++) {
                    const int cl = j * 16 + tx;
                    s[i][j] = (cl > rl) ? -1e30f : s[i][j] * scale;
                }
            }
        } else {
#pragma unroll
            for (int i = 0; i < 4; i++)
#pragma unroll
                for (int j = 0; j < 4; j++) s[i][j] *= scale;
        }

        float p[4][4];
#pragma unroll
        for (int i = 0; i < 4; i++) {
            float mx = s[i][0];
#pragma unroll
            for (int j = 1; j < 4; j++) mx = fmaxf(mx, s[i][j]);
#pragma unroll
            for (int off = 1; off < 16; off <<= 1)
                mx = fmaxf(mx, __shfl_xor_sync(0xffffffffu, mx, off));
            const float mnew = fmaxf(m[i], mx);
            const float aexp = __expf(m[i] - mnew);
            float rsum = 0.f;
#pragma unroll
            for (int j = 0; j < 4; j++) {
                p[i][j] = __expf(s[i][j] - mnew);
                rsum += p[i][j];
            }
#pragma unroll
            for (int off = 1; off < 16; off <<= 1)
                rsum += __shfl_xor_sync(0xffffffffu, rsum, off);
            l[i] = l[i] * aexp + rsum;
            m[i] = mnew;
#pragma unroll
            for (int j = 0; j < 4; j++) o[i][j] *= aexp;
        }

        __syncthreads();
#pragma unroll
        for (int i = 0; i < 4; i++)
#pragma unroll
            for (int j = 0; j < 4; j++)
                sKP[(i * 16 + ty) * ATT_LDS + (j * 16 + tx)] = p[i][j];
        __syncthreads();

        for (int c = 0; c < 64; c++) {
            float pp[4], vv[4];
#pragma unroll
            for (int i = 0; i < 4; i++) pp[i] = sKP[(i * 16 + ty) * ATT_LDS + c];
#pragma unroll
            for (int j = 0; j < 4; j++) vv[j] = sV[c * ATT_LDS + (j * 16 + tx)];
#pragma unroll
            for (int i = 0; i < 4; i++)
#pragma unroll
                for (int j = 0; j < 4; j++) o[i][j] += pp[i] * vv[j];
        }
    }

#pragma unroll
    for (int i = 0; i < 4; i++) {
        const float inv = 1.f / l[i];
        const int rg = q0 + i * 16 + ty;
#pragma unroll
        for (int j = 0; j < 4; j++)
            O[(baseRow + rg) * D_MODEL + hcol + (j * 16 + tx)] = o[i][j] * inv;
    }
}

// ---------------------------------------------------------------------------
extern "C" void kernel_launch(void* const* d_in, const int* in_sizes, int n_in,
                              void* d_out, int out_size)
{
    (void)in_sizes; (void)n_in; (void)out_size;
    const float* ctx = (const float*)d_in[0];
    const float* val = (const float*)d_in[1];
    const float* Wq  = (const float*)d_in[3];
    const float* bq  = (const float*)d_in[4];
    const float* Wk  = (const float*)d_in[5];
    const float* bk  = (const float*)d_in[6];
    const float* Wv  = (const float*)d_in[7];
    const float* bv  = (const float*)d_in[8];
    const float* Wo  = (const float*)d_in[9];
    const float* bo  = (const float*)d_in[10];
    float* out = (float*)d_out;

    float *qp, *kp, *vp, *ap;
    cudaGetSymbolAddress((void**)&qp, g_Q);
    cudaGetSymbolAddress((void**)&kp, g_K);
    cudaGetSymbolAddress((void**)&vp, g_V);
    cudaGetSymbolAddress((void**)&ap, g_A);

    cudaFuncSetAttribute(gemm_tf32_kernel,
                         cudaFuncAttributeMaxDynamicSharedMemorySize,
                         GEMM_SMEM_BYTES);
    cudaFuncSetAttribute(attn_kernel,
                         cudaFuncAttributeMaxDynamicSharedMemorySize,
                         ATT_SMEM_BYTES);

    dim3 gblock(256);
    dim3 ggrid(D_MODEL / BN, MROWS / BM);  // (8, 64)

    gemm_tf32_kernel<<<ggrid, gblock, GEMM_SMEM_BYTES>>>(ctx, Wq, bq, qp);
    gemm_tf32_kernel<<<ggrid, gblock, GEMM_SMEM_BYTES>>>(ctx, Wk, bk, kp);
    gemm_tf32_kernel<<<ggrid, gblock, GEMM_SMEM_BYTES>>>(val, Wv, bv, vp);

    dim3 agrid(SEQ / 64, NH, BATCH);  // (32, 16, 4)
    attn_kernel<<<agrid, 256, ATT_SMEM_BYTES>>>(qp, kp, vp, ap);

    gemm_tf32_kernel<<<ggrid, gblock, GEMM_SMEM_BYTES>>>(ap, Wo, bo, out);
}

// round 3
// speedup vs baseline: 4.3905x; 2.5051x over previous
#include <cuda_runtime.h>
#include <cstdint>

// Problem constants (fixed by the reference)
#define D_MODEL 1024
#define SEQ     2048
#define BATCH   4
#define NH      16
#define DK      64
#define MROWS   (BATCH * SEQ)   // 8192

// Scratch (no allocations allowed)
__device__ float g_Q[(size_t)MROWS * D_MODEL];
__device__ float g_K[(size_t)MROWS * D_MODEL];
__device__ float g_V[(size_t)MROWS * D_MODEL];
__device__ float g_A[(size_t)MROWS * D_MODEL];

__device__ __forceinline__ float f2tf32(float x) {
    uint32_t r;
    asm("cvt.rna.tf32.f32 %0, %1;" : "=r"(r) : "f"(x));
    return __uint_as_float(r);
}

__device__ __forceinline__ void mma_tf32(
    float& c0, float& c1, float& c2, float& c3,
    uint32_t a0, uint32_t a1, uint32_t a2, uint32_t a3,
    uint32_t b0, uint32_t b1)
{
    asm volatile(
        "mma.sync.aligned.m16n8k8.row.col.f32.tf32.tf32.f32 "
        "{%0,%1,%2,%3}, {%4,%5,%6,%7}, {%8,%9}, {%0,%1,%2,%3};"
        : "+f"(c0), "+f"(c1), "+f"(c2), "+f"(c3)
        : "r"(a0), "r"(a1), "r"(a2), "r"(a3), "r"(b0), "r"(b1));
}

// ---------------------------------------------------------------------------
// TF32 tensor-core GEMM: C[M,N] = A[M,K] @ W[K,N] + bias[N]  (unchanged R2)
// ---------------------------------------------------------------------------
#define BM 128
#define BN 128
#define BK 32
#define APITCH 36
#define BPITCH 136
#define ASTG (BM * APITCH)
#define BSTG (BK * BPITCH)
#define GEMM_SMEM_BYTES (2 * (ASTG + BSTG) * 4)

__global__ __launch_bounds__(256) void gemm_tf32_kernel(
    const float* __restrict__ A, const float* __restrict__ W,
    const float* __restrict__ bias, float* __restrict__ C)
{
    const int N = D_MODEL, K = D_MODEL;
    extern __shared__ float sm[];
    float* As = sm;
    float* Bs = sm + 2 * ASTG;

    const int tid  = threadIdx.x;
    const int lane = tid & 31;
    const int warp = tid >> 5;
    const int wm = (warp >> 2) * 64;
    const int wn = (warp & 3) * 32;
    const int rowBase = blockIdx.y * BM;
    const int colBase = blockIdx.x * BN;

    const int ar = tid >> 3;
    const int ac = (tid & 7) * 4;
    const int br = tid >> 5;
    const int bc = (tid & 31) * 4;

    const float* Abase = A + (size_t)(rowBase + ar) * K + ac;
    const float* Wbase = W + (size_t)br * N + colBase + bc;

    float acc[4][4][4];
#pragma unroll
    for (int i = 0; i < 4; i++)
#pragma unroll
        for (int j = 0; j < 4; j++)
#pragma unroll
            for (int q = 0; q < 4; q++) acc[i][j][q] = 0.f;

    float4 aReg[4], bReg[4];
#pragma unroll
    for (int i = 0; i < 4; i++) {
        aReg[i] = *(const float4*)(Abase + (size_t)(32 * i) * K);
        bReg[i] = *(const float4*)(Wbase + (size_t)(8 * i) * N);
    }
#pragma unroll
    for (int i = 0; i < 4; i++) {
        float* d = &As[(ar + 32 * i) * APITCH + ac];
        d[0] = f2tf32(aReg[i].x); d[1] = f2tf32(aReg[i].y);
        d[2] = f2tf32(aReg[i].z); d[3] = f2tf32(aReg[i].w);
        float* e = &Bs[(br + 8 * i) * BPITCH + bc];
        e[0] = f2tf32(bReg[i].x); e[1] = f2tf32(bReg[i].y);
        e[2] = f2tf32(bReg[i].z); e[3] = f2tf32(bReg[i].w);
    }
    __syncthreads();

    int stage = 0;
    for (int k0 = 0; k0 < K; k0 += BK) {
        const bool more = (k0 + BK) < K;
        if (more) {
#pragma unroll
            for (int i = 0; i < 4; i++) {
                aReg[i] = *(const float4*)(Abase + (size_t)(32 * i) * K + k0 + BK);
                bReg[i] = *(const float4*)(Wbase + (size_t)(k0 + BK + 8 * i) * N);
            }
        }
        const float* Acur = As + stage * ASTG;
        const float* Bcur = Bs + stage * BSTG;
#pragma unroll
        for (int kk = 0; kk < BK; kk += 8) {
            uint32_t af[4][4], bf[4][2];
#pragma unroll
            for (int i = 0; i < 4; i++) {
                const int r0 = wm + i * 16 + (lane >> 2);
                const int cc = kk + (lane & 3);
                af[i][0] = __float_as_uint(Acur[r0 * APITCH + cc]);
                af[i][1] = __float_as_uint(Acur[(r0 + 8) * APITCH + cc]);
                af[i][2] = __float_as_uint(Acur[r0 * APITCH + cc + 4]);
                af[i][3] = __float_as_uint(Acur[(r0 + 8) * APITCH + cc + 4]);
            }
#pragma unroll
            for (int j = 0; j < 4; j++) {
                const int cl = wn + j * 8 + (lane >> 2);
                const int kr = kk + (lane & 3);
                bf[j][0] = __float_as_uint(Bcur[kr * BPITCH + cl]);
                bf[j][1] = __float_as_uint(Bcur[(kr + 4) * BPITCH + cl]);
            }
#pragma unroll
            for (int i = 0; i < 4; i++)
#pragma unroll
                for (int j = 0; j < 4; j++)
                    mma_tf32(acc[i][j][0], acc[i][j][1], acc[i][j][2], acc[i][j][3],
                             af[i][0], af[i][1], af[i][2], af[i][3],
                             bf[j][0], bf[j][1]);
        }
        if (more) {
            float* Anx = As + (stage ^ 1) * ASTG;
            float* Bnx = Bs + (stage ^ 1) * BSTG;
#pragma unroll
            for (int i = 0; i < 4; i++) {
                float* d = &Anx[(ar + 32 * i) * APITCH + ac];
                d[0] = f2tf32(aReg[i].x); d[1] = f2tf32(aReg[i].y);
                d[2] = f2tf32(aReg[i].z); d[3] = f2tf32(aReg[i].w);
                float* e = &Bnx[(br + 8 * i) * BPITCH + bc];
                e[0] = f2tf32(bReg[i].x); e[1] = f2tf32(bReg[i].y);
                e[2] = f2tf32(bReg[i].z); e[3] = f2tf32(bReg[i].w);
            }
        }
        __syncthreads();
        stage ^= 1;
    }

#pragma unroll
    for (int j = 0; j < 4; j++) {
        const int col = colBase + wn + j * 8 + 2 * (lane & 3);
        const float b0 = bias[col], b1 = bias[col + 1];
#pragma unroll
        for (int i = 0; i < 4; i++) {
            const int r0 = rowBase + wm + i * 16 + (lane >> 2);
            float2 v0 = make_float2(acc[i][j][0] + b0, acc[i][j][1] + b1);
            float2 v1 = make_float2(acc[i][j][2] + b0, acc[i][j][3] + b1);
            *(float2*)&C[(size_t)r0 * N + col] = v0;
            *(float2*)&C[(size_t)(r0 + 8) * N + col] = v1;
        }
    }
}

// ---------------------------------------------------------------------------
// TF32 tensor-core flash attention (causal).
// CTA: 128 q-rows x (head, batch). 8 warps, 16 q-rows each. Key tiles of 64.
// Q pre-scaled by 1/8 (exact). P kept in registers (k-permutation trick):
// C-frag cols {2q,2q+1} feed A-frag slots {q,q+4}; V B-frag rows permuted to
// {2q,2q+1} to match.
// ---------------------------------------------------------------------------
#define FPITCH 68
#define ATT_SMEM_BYTES ((128 * FPITCH + 2 * 64 * FPITCH) * 4)   // 69632

__global__ __launch_bounds__(256, 2) void attn_tc_kernel(
    const float* __restrict__ Q, const float* __restrict__ K,
    const float* __restrict__ V, float* __restrict__ O)
{
    extern __shared__ float sm[];
    float* sQ = sm;                       // [128][68]
    float* sK = sm + 128 * FPITCH;        // [64][68]
    float* sV = sK + 64 * FPITCH;         // [64][68]

    const int tid  = threadIdx.x;
    const int lane = tid & 31;
    const int warp = tid >> 5;
    const int g  = lane >> 2;   // 0..7
    const int q4 = lane & 3;    // 0..3
    const int qt = blockIdx.x;
    const int h  = blockIdx.y;
    const int b  = blockIdx.z;
    const int q0 = qt * 128;
    const size_t base = (size_t)b * SEQ;
    const int hcol = h * DK;

    // Load Q tile (scaled by 1/8, tf32-rounded)
    {
        const int r  = tid >> 4;          // 0..15
        const int c4 = (tid & 15) * 4;    // 0..60
#pragma unroll
        for (int rr = 0; rr < 128; rr += 16) {
            float4 v = *(const float4*)&Q[(base + q0 + rr + r) * D_MODEL + hcol + c4];
            float* d = &sQ[(rr + r) * FPITCH + c4];
            d[0] = f2tf32(v.x * 0.125f); d[1] = f2tf32(v.y * 0.125f);
            d[2] = f2tf32(v.z * 0.125f); d[3] = f2tf32(v.w * 0.125f);
        }
    }
    __syncthreads();

    // Hoist Q fragments to registers (reused for every key tile)
    uint32_t qf[8][4];
    {
        const int r0 = warp * 16 + g;
#pragma unroll
        for (int kk = 0; kk < 8; kk++) {
            const int c = kk * 8 + q4;
            qf[kk][0] = __float_as_uint(sQ[r0 * FPITCH + c]);
            qf[kk][1] = __float_as_uint(sQ[(r0 + 8) * FPITCH + c]);
            qf[kk][2] = __float_as_uint(sQ[r0 * FPITCH + c + 4]);
            qf[kk][3] = __float_as_uint(sQ[(r0 + 8) * FPITCH + c + 4]);
        }
    }

    float oacc[8][4];
#pragma unroll
    for (int j = 0; j < 8; j++)
#pragma unroll
        for (int q = 0; q < 4; q++) oacc[j][q] = 0.f;
    float mrow[2] = {-1e30f, -1e30f};
    float lrow[2] = {0.f, 0.f};

    const int r0g = q0 + warp * 16 + g;   // global row of this thread's first row
    const int nkt = 2 * qt + 2;

    for (int kt = 0; kt < nkt; kt++) {
        const int k0 = kt * 64;
        __syncthreads();   // prior PV reads done before overwrite
        {
            const int r  = tid >> 4;
            const int c4 = (tid & 15) * 4;
#pragma unroll
            for (int rr = 0; rr < 64; rr += 16) {
                float4 kv = *(const float4*)&K[(base + k0 + rr + r) * D_MODEL + hcol + c4];
                float* dk = &sK[(rr + r) * FPITCH + c4];
                dk[0] = f2tf32(kv.x); dk[1] = f2tf32(kv.y);
                dk[2] = f2tf32(kv.z); dk[3] = f2tf32(kv.w);
                float4 vv = *(const float4*)&V[(base + k0 + rr + r) * D_MODEL + hcol + c4];
                float* dv = &sV[(rr + r) * FPITCH + c4];
                dv[0] = f2tf32(vv.x); dv[1] = f2tf32(vv.y);
                dv[2] = f2tf32(vv.z); dv[3] = f2tf32(vv.w);
            }
        }
        __syncthreads();

        // S = Q @ K^T  (already scaled via Q)
        float sacc[8][4];
#pragma unroll
        for (int j = 0; j < 8; j++)
#pragma unroll
            for (int q = 0; q < 4; q++) sacc[j][q] = 0.f;

#pragma unroll
        for (int kk = 0; kk < 8; kk++) {
#pragma unroll
            for (int j = 0; j < 8; j++) {
                const uint32_t b0 = __float_as_uint(sK[(j * 8 + g) * FPITCH + kk * 8 + q4]);
                const uint32_t b1 = __float_as_uint(sK[(j * 8 + g) * FPITCH + kk * 8 + q4 + 4]);
                mma_tf32(sacc[j][0], sacc[j][1], sacc[j][2], sacc[j][3],
                         qf[kk][0], qf[kk][1], qf[kk][2], qf[kk][3], b0, b1);
            }
        }

        // Causal mask (only the two diagonal-adjacent tiles need it)
        if (kt >= 2 * qt) {
#pragma unroll
            for (int j = 0; j < 8; j++) {
                const int c = k0 + j * 8 + 2 * q4;
                if (c     > r0g)     sacc[j][0] = -1e30f;
                if (c + 1 > r0g)     sacc[j][1] = -1e30f;
                if (c     > r0g + 8) sacc[j][2] = -1e30f;
                if (c + 1 > r0g + 8) sacc[j][3] = -1e30f;
            }
        }

        // Online softmax (two rows per thread; quad = lanes sharing a row)
#pragma unroll
        for (int hf = 0; hf < 2; hf++) {
            float mx = -1e30f;
#pragma unroll
            for (int j = 0; j < 8; j++)
                mx = fmaxf(mx, fmaxf(sacc[j][2 * hf], sacc[j][2 * hf + 1]));
            mx = fmaxf(mx, __shfl_xor_sync(0xffffffffu, mx, 1));
            mx = fmaxf(mx, __shfl_xor_sync(0xffffffffu, mx, 2));
            const float mnew = fmaxf(mrow[hf], mx);
            const float aexp = __expf(mrow[hf] - mnew);
            float rsum = 0.f;
#pragma unroll
            for (int j = 0; j < 8; j++) {
                float p0 = __expf(sacc[j][2 * hf]     - mnew);
                float p1 = __expf(sacc[j][2 * hf + 1] - mnew);
                rsum += p0 + p1;
                sacc[j][2 * hf]     = f2tf32(p0);
                sacc[j][2 * hf + 1] = f2tf32(p1);
            }
            rsum += __shfl_xor_sync(0xffffffffu, rsum, 1);
            rsum += __shfl_xor_sync(0xffffffffu, rsum, 2);
            lrow[hf] = lrow[hf] * aexp + rsum;
            mrow[hf] = mnew;
#pragma unroll
            for (int j = 0; j < 8; j++) {
                oacc[j][2 * hf]     *= aexp;
                oacc[j][2 * hf + 1] *= aexp;
            }
        }

        // O += P @ V  (P in registers; V rows permuted {2q,2q+1} per slot)
#pragma unroll
        for (int kk = 0; kk < 8; kk++) {
            const uint32_t a0 = __float_as_uint(sacc[kk][0]);
            const uint32_t a1 = __float_as_uint(sacc[kk][2]);
            const uint32_t a2 = __float_as_uint(sacc[kk][1]);
            const uint32_t a3 = __float_as_uint(sacc[kk][3]);
#pragma unroll
            for (int j = 0; j < 8; j++) {
                const uint32_t b0 = __float_as_uint(sV[(kk * 8 + 2 * q4)     * FPITCH + j * 8 + g]);
                const uint32_t b1 = __float_as_uint(sV[(kk * 8 + 2 * q4 + 1) * FPITCH + j * 8 + g]);
                mma_tf32(oacc[j][0], oacc[j][1], oacc[j][2], oacc[j][3],
                         a0, a1, a2, a3, b0, b1);
            }
        }
    }

    // Normalize + store
    const float inv0 = 1.f / lrow[0];
    const float inv1 = 1.f / lrow[1];
#pragma unroll
    for (int j = 0; j < 8; j++) {
        const int col = hcol + j * 8 + 2 * q4;
        float2 v0 = make_float2(oacc[j][0] * inv0, oacc[j][1] * inv0);
        float2 v1 = make_float2(oacc[j][2] * inv1, oacc[j][3] * inv1);
        *(float2*)&O[(base + r0g)     * D_MODEL + col] = v0;
        *(float2*)&O[(base + r0g + 8) * D_MODEL + col] = v1;
    }
}

// ---------------------------------------------------------------------------
extern "C" void kernel_launch(void* const* d_in, const int* in_sizes, int n_in,
                              void* d_out, int out_size)
{
    (void)in_sizes; (void)n_in; (void)out_size;
    const float* ctx = (const float*)d_in[0];
    const float* val = (const float*)d_in[1];
    const float* Wq  = (const float*)d_in[3];
    const float* bq  = (const float*)d_in[4];
    const float* Wk  = (const float*)d_in[5];
    const float* bk  = (const float*)d_in[6];
    const float* Wv  = (const float*)d_in[7];
    const float* bv  = (const float*)d_in[8];
    const float* Wo  = (const float*)d_in[9];
    const float* bo  = (const float*)d_in[10];
    float* out = (float*)d_out;

    float *qp, *kp, *vp, *ap;
    cudaGetSymbolAddress((void**)&qp, g_Q);
    cudaGetSymbolAddress((void**)&kp, g_K);
    cudaGetSymbolAddress((void**)&vp, g_V);
    cudaGetSymbolAddress((void**)&ap, g_A);

    cudaFuncSetAttribute(gemm_tf32_kernel,
                         cudaFuncAttributeMaxDynamicSharedMemorySize,
                         GEMM_SMEM_BYTES);
    cudaFuncSetAttribute(attn_tc_kernel,
                         cudaFuncAttributeMaxDynamicSharedMemorySize,
                         ATT_SMEM_BYTES);

    dim3 gblock(256);
    dim3 ggrid(D_MODEL / BN, MROWS / BM);  // (8, 64)

    gemm_tf32_kernel<<<ggrid, gblock, GEMM_SMEM_BYTES>>>(ctx, Wq, bq, qp);
    gemm_tf32_kernel<<<ggrid, gblock, GEMM_SMEM_BYTES>>>(ctx, Wk, bk, kp);
    gemm_tf32_kernel<<<ggrid, gblock, GEMM_SMEM_BYTES>>>(val, Wv, bv, vp);

    dim3 agrid(SEQ / 128, NH, BATCH);  // (16, 16, 4)
    attn_tc_kernel<<<agrid, 256, ATT_SMEM_BYTES>>>(qp, kp, vp, ap);

    gemm_tf32_kernel<<<ggrid, gblock, GEMM_SMEM_BYTES>>>(ap, Wo, bo, out);
}